// round 6
// baseline (speedup 1.0000x reference)
#include <cuda_runtime.h>
#include <math.h>

#define NB      32
#define SAMPLES 5000
#define HW      (512 * 1024)
#define TOTAL   (NB * SAMPLES)          // 160000 pairs
#define TOTAL2  (TOTAL * 2)             // 320000 threads (one per pair-side)
#define SIGMA   0.03f
#define EPS     1e-6f

#define THREADS 256
#define BLOCKS  (TOTAL2 / THREADS)      // 1250 exactly

// zero-initialized at load; reset by last block each call (graph-safe)
__device__ float        g_acc[2];       // [0]=loss sum, [1]=valid count
__device__ unsigned int g_count;

__global__ void __launch_bounds__(THREADS) rl_fused4_kernel(
    const float* __restrict__ pred,
    const float* __restrict__ targ,
    const int*   __restrict__ mask,     // bool upcast to int32 by harness
    const int*   __restrict__ idxA,
    const int*   __restrict__ idxB,
    float*       __restrict__ out)
{
    int i = blockIdx.x * blockDim.x + threadIdx.x;   // < TOTAL2 always

    int pair = i >> 1;
    int side = i & 1;                                // 0 = A-lane, 1 = B-lane
    int n    = pair / SAMPLES;
    long long base = (long long)n * (long long)HW;

    int a = idxA[pair];                 // coalesced (lanes of a pair merge)
    int b = idxB[pair];
    long long gA = base + (long long)a;
    long long gB = base + (long long)b;
    long long g  = side ? gB : gA;

    // DEPTH-1 CHAIN: issue all 4 independent gathers back-to-back.
    // mask[gA]/mask[gB] are duplicated across the pair's 2 adjacent lanes
    // -> merged in L1TEX, no extra DRAM traffic.
    int   mA = mask[gA];
    int   mB = mask[gB];
    float t  = targ[g];
    float p  = pred[g];

    bool cm = (mA != 0) && (mB != 0);

    // single pair-exchange at the end
    float tO = __shfl_xor_sync(0xffffffffu, t, 1);
    float pO = __shfl_xor_sync(0xffffffffu, p, 1);

    float loss = 0.0f, valid = 0.0f;
    if (side == 0 && cm) {               // even lane owns the pair's loss
        float tA = t,  tB = tO;
        float pA = p,  pB = pO;

        float ratio = tA / (tB + EPS);
        const float hi = 1.0f + SIGMA;
        const float lo = 1.0f / (1.0f + SIGMA);
        bool mask_eq = (ratio < hi) && (ratio > lo);

        valid = 1.0f;
        if (mask_eq) {
            float d = pA - pB;
            loss = d * d;                        // equal branch (ALPHA=1)
        } else {
            float label = (ratio >= hi) ? 1.0f : -1.0f;
            float x = (pB - pA) * label;
            loss = (x > 20.0f) ? x : log1pf(expf(x));
        }
    }

    // --- block reduction of (loss, valid) ---
    #pragma unroll
    for (int off = 16; off > 0; off >>= 1) {
        loss  += __shfl_down_sync(0xffffffffu, loss,  off);
        valid += __shfl_down_sync(0xffffffffu, valid, off);
    }

    __shared__ float s_loss[8], s_valid[8];
    __shared__ bool  s_last;
    int lane = threadIdx.x & 31;
    int wid  = threadIdx.x >> 5;
    if (lane == 0) {
        s_loss[wid]  = loss;
        s_valid[wid] = valid;
    }
    __syncthreads();

    if (wid == 0) {
        loss  = (lane < (THREADS / 32)) ? s_loss[lane]  : 0.0f;
        valid = (lane < (THREADS / 32)) ? s_valid[lane] : 0.0f;
        #pragma unroll
        for (int off = 4; off > 0; off >>= 1) {
            loss  += __shfl_down_sync(0xffffffffu, loss,  off);
            valid += __shfl_down_sync(0xffffffffu, valid, off);
        }
        if (lane == 0) {
            atomicAdd(&g_acc[0], loss);
            atomicAdd(&g_acc[1], valid);
            __threadfence();
            unsigned ticket = atomicAdd(&g_count, 1u);
            s_last = (ticket == (unsigned)(gridDim.x - 1));
        }
    }
    __syncthreads();

    // last block finalizes and resets state for next graph replay
    if (s_last && threadIdx.x == 0) {
        float l = g_acc[0], v = g_acc[1];
        out[0] = l / (v + EPS);          // ALPHA = LOSS_WEIGHT = 1
        g_acc[0] = 0.0f;
        g_acc[1] = 0.0f;
        __threadfence();
        g_count = 0u;
    }
}

extern "C" void kernel_launch(void* const* d_in, const int* in_sizes, int n_in,
                              void* d_out, int out_size)
{
    const float* pred = (const float*)d_in[0];
    const float* targ = (const float*)d_in[1];
    const int*   mask = (const int*)d_in[2];
    const int*   idxA = (const int*)d_in[3];
    const int*   idxB = (const int*)d_in[4];
    float* out = (float*)d_out;

    rl_fused4_kernel<<<BLOCKS, THREADS>>>(pred, targ, mask, idxA, idxB, out);
}

// round 7
// speedup vs baseline: 1.3488x; 1.3488x over previous
#include <cuda_runtime.h>
#include <math.h>

#define NB      32
#define SAMPLES 5000
#define HW      (512 * 1024)
#define TOTAL   (NB * SAMPLES)          // 160000 pairs
#define SIGMA   0.03f
#define EPS     1e-6f

#define THREADS 256
#define BLOCKS  ((TOTAL + THREADS - 1) / THREADS)   // 625

// zero-initialized at load; reset by last block each call (graph-safe)
__device__ float        g_acc[2];       // [0]=loss sum, [1]=valid count
__device__ unsigned int g_count;

__global__ void __launch_bounds__(THREADS) rl_fused5_kernel(
    const float* __restrict__ pred,
    const float* __restrict__ targ,
    const int*   __restrict__ mask,     // bool upcast to int32 by harness
    const int*   __restrict__ idxA,
    const int*   __restrict__ idxB,
    float*       __restrict__ out)
{
    int i = blockIdx.x * blockDim.x + threadIdx.x;

    float loss = 0.0f, valid = 0.0f;

    if (i < TOTAL) {
        int n = i / SAMPLES;
        long long base = (long long)n * (long long)HW;
        long long ia = base + (long long)idxA[i];
        long long ib = base + (long long)idxB[i];

        // 2 independent mask gathers (depth-1, MLP=2)
        int mA = mask[ia];
        int mB = mask[ib];

        if (mA && mB) {                 // ~25% of pairs; warp-predicated LDGs
            valid = 1.0f;
            // 4 independent gathers (depth-2 overall, MLP=4)
            float tA = targ[ia];
            float tB = targ[ib];
            float pA = pred[ia];
            float pB = pred[ib];

            float ratio = tA / (tB + EPS);
            const float hi = 1.0f + SIGMA;
            const float lo = 1.0f / (1.0f + SIGMA);

            if (ratio < hi && ratio > lo) {
                float d = pA - pB;
                loss = d * d;                       // equal branch (ALPHA=1)
            } else {
                float label = (ratio >= hi) ? 1.0f : -1.0f;
                float x = (pB - pA) * label;
                loss = (x > 20.0f) ? x : log1pf(expf(x));
            }
        }
    }

    // --- block reduction of (loss, valid) ---
    #pragma unroll
    for (int off = 16; off > 0; off >>= 1) {
        loss  += __shfl_down_sync(0xffffffffu, loss,  off);
        valid += __shfl_down_sync(0xffffffffu, valid, off);
    }

    __shared__ float s_loss[8], s_valid[8];
    __shared__ bool  s_last;
    int lane = threadIdx.x & 31;
    int wid  = threadIdx.x >> 5;
    if (lane == 0) {
        s_loss[wid]  = loss;
        s_valid[wid] = valid;
    }
    __syncthreads();

    if (wid == 0) {
        loss  = (lane < (THREADS / 32)) ? s_loss[lane]  : 0.0f;
        valid = (lane < (THREADS / 32)) ? s_valid[lane] : 0.0f;
        #pragma unroll
        for (int off = 4; off > 0; off >>= 1) {
            loss  += __shfl_down_sync(0xffffffffu, loss,  off);
            valid += __shfl_down_sync(0xffffffffu, valid, off);
        }
        if (lane == 0) {
            atomicAdd(&g_acc[0], loss);
            atomicAdd(&g_acc[1], valid);
            __threadfence();
            unsigned ticket = atomicAdd(&g_count, 1u);
            s_last = (ticket == (unsigned)(gridDim.x - 1));
        }
    }
    __syncthreads();

    // last block finalizes and resets state for next graph replay
    if (s_last && threadIdx.x == 0) {
        float l = g_acc[0], v = g_acc[1];
        out[0] = l / (v + EPS);          // ALPHA = LOSS_WEIGHT = 1
        g_acc[0] = 0.0f;
        g_acc[1] = 0.0f;
        __threadfence();
        g_count = 0u;
    }
}

extern "C" void kernel_launch(void* const* d_in, const int* in_sizes, int n_in,
                              void* d_out, int out_size)
{
    const float* pred = (const float*)d_in[0];
    const float* targ = (const float*)d_in[1];
    const int*   mask = (const int*)d_in[2];
    const int*   idxA = (const int*)d_in[3];
    const int*   idxB = (const int*)d_in[4];
    float* out = (float*)d_out;

    rl_fused5_kernel<<<BLOCKS, THREADS>>>(pred, targ, mask, idxA, idxB, out);
}

// round 8
// speedup vs baseline: 1.3810x; 1.0238x over previous
#include <cuda_runtime.h>
#include <math.h>

#define NB      32
#define SAMPLES 5000
#define HW      (512 * 1024)
#define TOTAL   (NB * SAMPLES)          // 160000 pairs
#define K       5                        // pairs per thread
#define NTHR    (TOTAL / K)              // 32000 threads
#define THREADS 256
#define BLOCKS  (NTHR / THREADS)         // 125 exactly
#define SIGMA   0.03f
#define EPS     1e-6f

// zero-initialized at load; reset by last block each call (graph-safe)
__device__ float        g_acc[2];        // [0]=loss sum, [1]=valid count
__device__ unsigned int g_count;

__global__ void __launch_bounds__(THREADS) rl_fused6_kernel(
    const float* __restrict__ pred,
    const float* __restrict__ targ,
    const int*   __restrict__ mask,      // bool upcast to int32 by harness
    const int*   __restrict__ idxA,
    const int*   __restrict__ idxB,
    float*       __restrict__ out)
{
    int t = blockIdx.x * blockDim.x + threadIdx.x;   // < NTHR always

    // pair j handled by this thread: t + j*NTHR  (coalesced idx loads)
    long long gA[K], gB[K];
    #pragma unroll
    for (int j = 0; j < K; j++) {
        int pair = t + j * NTHR;
        int n    = pair / SAMPLES;
        long long base = (long long)n * (long long)HW;
        gA[j] = base + (long long)idxA[pair];
        gB[j] = base + (long long)idxB[pair];
    }

    // phase A: 2K independent mask gathers, all in flight together
    int mA[K], mB[K];
    #pragma unroll
    for (int j = 0; j < K; j++) {
        mA[j] = mask[gA[j]];
        mB[j] = mask[gB[j]];
    }

    bool cm[K];
    #pragma unroll
    for (int j = 0; j < K; j++) cm[j] = (mA[j] != 0) && (mB[j] != 0);

    // phase B: all conditional t/p gathers batched (predicated LDGs)
    float tA[K], tB[K], pA[K], pB[K];
    #pragma unroll
    for (int j = 0; j < K; j++) {
        tA[j] = 1.0f; tB[j] = 1.0f; pA[j] = 0.0f; pB[j] = 0.0f;
        if (cm[j]) {
            tA[j] = targ[gA[j]];
            tB[j] = targ[gB[j]];
            pA[j] = pred[gA[j]];
            pB[j] = pred[gB[j]];
        }
    }

    // compute
    float loss = 0.0f, valid = 0.0f;
    const float hi = 1.0f + SIGMA;
    const float lo = 1.0f / (1.0f + SIGMA);
    #pragma unroll
    for (int j = 0; j < K; j++) {
        if (cm[j]) {
            valid += 1.0f;
            float ratio = tA[j] / (tB[j] + EPS);
            if (ratio < hi && ratio > lo) {
                float d = pA[j] - pB[j];
                loss += d * d;                        // equal branch (ALPHA=1)
            } else {
                float label = (ratio >= hi) ? 1.0f : -1.0f;
                float x = (pB[j] - pA[j]) * label;
                loss += (x > 20.0f) ? x : log1pf(expf(x));
            }
        }
    }

    // --- block reduction of (loss, valid) ---
    #pragma unroll
    for (int off = 16; off > 0; off >>= 1) {
        loss  += __shfl_down_sync(0xffffffffu, loss,  off);
        valid += __shfl_down_sync(0xffffffffu, valid, off);
    }

    __shared__ float s_loss[8], s_valid[8];
    __shared__ bool  s_last;
    int lane = threadIdx.x & 31;
    int wid  = threadIdx.x >> 5;
    if (lane == 0) {
        s_loss[wid]  = loss;
        s_valid[wid] = valid;
    }
    __syncthreads();

    if (wid == 0) {
        loss  = (lane < (THREADS / 32)) ? s_loss[lane]  : 0.0f;
        valid = (lane < (THREADS / 32)) ? s_valid[lane] : 0.0f;
        #pragma unroll
        for (int off = 4; off > 0; off >>= 1) {
            loss  += __shfl_down_sync(0xffffffffu, loss,  off);
            valid += __shfl_down_sync(0xffffffffu, valid, off);
        }
        if (lane == 0) {
            atomicAdd(&g_acc[0], loss);
            atomicAdd(&g_acc[1], valid);
            __threadfence();
            unsigned ticket = atomicAdd(&g_count, 1u);
            s_last = (ticket == (unsigned)(gridDim.x - 1));
        }
    }
    __syncthreads();

    // last block finalizes and resets state for next graph replay
    if (s_last && threadIdx.x == 0) {
        float l = g_acc[0], v = g_acc[1];
        out[0] = l / (v + EPS);           // ALPHA = LOSS_WEIGHT = 1
        g_acc[0] = 0.0f;
        g_acc[1] = 0.0f;
        __threadfence();
        g_count = 0u;
    }
}

extern "C" void kernel_launch(void* const* d_in, const int* in_sizes, int n_in,
                              void* d_out, int out_size)
{
    const float* pred = (const float*)d_in[0];
    const float* targ = (const float*)d_in[1];
    const int*   mask = (const int*)d_in[2];
    const int*   idxA = (const int*)d_in[3];
    const int*   idxB = (const int*)d_in[4];
    float* out = (float*)d_out;

    rl_fused6_kernel<<<BLOCKS, THREADS>>>(pred, targ, mask, idxA, idxB, out);
}